// round 17
// baseline (speedup 1.0000x reference)
#include <cuda_runtime.h>
#include <cstddef>

// ManyBodyVoxel: out[0, a, c=t*2+l, x, y, z] =
//   sum_n exp(coeff * || grid_l[x,y,z] - d[a,n]*mask_t[a,n] ||^2)
// R17: R16 fused single-barrier prologue + atom-split consumer groups:
//      512 CTAs (a,l,xh) x 512 threads; group1 (warps 0-7, also prologue)
//      accumulates odd... even/odd slots and STS partials (double-buffered),
//      group0 adds + stores. ~86% occupancy, per-thread chains halved.

#define NT 512

typedef unsigned long long u64;

__device__ __forceinline__ u64 pk2(float v) {
    u64 r; asm("mov.b64 %0, {%1, %2};" : "=l"(r) : "f"(v), "f"(v)); return r;
}
__device__ __forceinline__ u64 fma2(u64 a, u64 b, u64 c) {
    u64 d; asm("fma.rn.f32x2 %0, %1, %2, %3;" : "=l"(d) : "l"(a), "l"(b), "l"(c)); return d;
}
__device__ __forceinline__ u64 mul2(u64 a, u64 b) {
    u64 d; asm("mul.rn.f32x2 %0, %1, %2;" : "=l"(d) : "l"(a), "l"(b)); return d;
}
__device__ __forceinline__ u64 add2(u64 a, u64 b) {
    u64 d; asm("add.rn.f32x2 %0, %1, %2;" : "=l"(d) : "l"(a), "l"(b)); return d;
}
__device__ __forceinline__ void unpk(u64 v, float& lo, float& hi) {
    asm("mov.b64 {%0, %1}, %2;" : "=f"(lo), "=f"(hi) : "l"(v));
}

__global__ __launch_bounds__(NT, 4)
void mbv_kernel(const float* __restrict__ dist,   // (1,128,64,3) fp32
                const float* __restrict__ sigma,  // (1,) fp32
                const int*   __restrict__ anum,   // (128,64) int64 or int32 (auto-detect)
                float* __restrict__ out)          // (1,128,10,16,16,16) fp32
{
    const int b    = blockIdx.x;
    const int xh   = b & 1;           // x half: [xh*8, xh*8+8)
    const int l    = (b >> 1) & 1;    // 0: L=8, 1: L=12
    const int a    = b >> 2;
    const int tid  = threadIdx.x;
    const int w    = tid >> 5;
    const int lane = tid & 31;
    const int rest = tid & 255;       // (yy, zz) shared by thread pair (tid, tid^256)
    const int zz   = rest & 15;
    const int yy   = rest >> 4;
    // group: warps 0-7 (prologue workers) get the lighter consumer role (1)
    const int g    = (tid < 256) ? 1 : 0;

    // Record (slot): 64 floats = 256B. x[16] @ +0, y[16] @ +64B, z[16] @ +128B.
    __shared__ __align__(16) float tab[65 * 64];
    __shared__ __align__(16) float red[2][256 * 8];   // double-buffered partials
    __shared__ int startc_s[5];
    __shared__ int cntc_s[5];

    const float s  = sigma[0];
    const float cf = -0.5f / (s * s);

    // ---- Fused prologue (warps 0-7 only): classify + exp rows, one barrier ----
    if (w < 8) {
        const int n_my = 8 * w + (lane >> 2);   // 8 warps x 8 atoms = 64 atoms
        const int ax   = lane & 3;              // 0..2 axis; 3 = base role (w0)
        float dv_my = 0.0f;
        if (ax < 3) dv_my = __ldg(&dist[(a * 64 + n_my) * 3 + ax]);

        int4 q = ((const int4*)anum)[a * 32 + lane];   // int64 view
        int2 r = ((const int2*)anum)[a * 32 + lane];   // int32 view
        bool i32 = __any_sync(0xffffffffu, (q.y | q.w) != 0);
        int z0 = i32 ? r.x : q.x;
        int z1 = i32 ? r.y : q.z;

        unsigned lt = (1u << lane) - 1u;
        const int ZT[5] = {1, 6, 7, 8, 16};
        int code0 = 0, code1 = 0;
        int base = 0;
        int myst = 0, mycnt = 0;
        #pragma unroll
        for (int t = 0; t < 5; t++) {
            unsigned m0 = __ballot_sync(0xffffffffu, z0 == ZT[t]);
            unsigned m1 = __ballot_sync(0xffffffffu, z1 == ZT[t]);
            int c0 = __popc(m0), c = c0 + __popc(m1);
            if (z0 == ZT[t]) code0 = (base + __popc(m0 & lt)) | 0x100;
            if (z1 == ZT[t]) code1 = (base + c0 + __popc(m1 & lt)) | 0x100;
            if (lane == t) { myst = base; mycnt = c; }   // lane t keeps type t's meta
            base += c;
        }
        if (w == 0 && lane < 5) { startc_s[lane] = myst; cntc_s[lane] = mycnt; }

        int src = n_my >> 1;
        int cA = __shfl_sync(0xffffffffu, code0, src);
        int cB = __shfl_sync(0xffffffffu, code1, src);
        int code = (n_my & 1) ? cB : cA;

        int recid = -1, wax = ax;
        float dv = dv_my;
        if (ax < 3) {
            if (code & 0x100) recid = code & 0xff;
        } else if (w == 0 && (lane >> 2) < 3) {   // lanes 3,7,11: base axes 0..2
            recid = 64; wax = lane >> 2; dv = 0.0f;
        }
        if (recid >= 0) {
            const float Lp   = l ? 12.0f : 8.0f;
            const float half = 0.5f * Lp;
            const float step = Lp * (1.0f / 15.0f);
            const float Brat = __expf(2.0f * cf * step * step);
            float* dst = &tab[recid * 64 + wax * 16];

            float bse = -half - dv;
            int jc = __float2int_rn(-bse / step);
            jc = max(0, min(15, jc));
            float uc = bse + step * (float)jc;
            float fc = __expf(cf * uc * uc);
            float ru = __expf(cf * step * (2.0f * uc + step));
            float rd = __expf(cf * step * (step - 2.0f * uc));
            dst[jc] = fc;
            float f = fc, rr = ru;
            for (int j = jc + 1; j < 16; j++) { f *= rr; rr *= Brat; dst[j] = f; }
            f = fc; rr = rd;
            for (int j = jc - 1; j >= 0; j--) { f *= rr; rr *= Brat; dst[j] = f; }
        }
    }

    __syncthreads();

    // ---- Consumer: thread pair (tid, tid^256) splits the atom stream ----
    const char* tb = reinterpret_cast<const char*>(tab);
    const int offX = xh * 32;
    const int offy = 64 + yy * 4;
    const int offz = 128 + zz * 4;

    const char* br = tb + 64 * 256;    // base record
    const float byz = *(const float*)(br + offy) * *(const float*)(br + offz);
    const ulonglong2 BXa = *(const ulonglong2*)(br + offX);
    const ulonglong2 BXb = *(const ulonglong2*)(br + offX + 16);

    float* op = out + (((size_t)(a * 10 + l)) << 12) + ((size_t)xh << 11)
                    + ((size_t)yy << 4) + (size_t)zz;

    ulonglong2* myred = reinterpret_cast<ulonglong2*>(&red[0][rest * 8]);
    const int bufstride = (256 * 8) / 2;   // in ulonglong2 units... (floats/2? see below)

    #pragma unroll
    for (int t = 0; t < 5; t++) {
        const int c  = cntc_s[t];
        const int st = startc_s[t];
        // group 0 carries the base term; group 1 starts at zero
        const u64 bw = pk2(g ? 0.0f : (float)(64 - c) * byz);
        u64 a0 = mul2(bw, BXa.x);
        u64 a1 = mul2(bw, BXa.y);
        u64 a2 = mul2(bw, BXb.x);
        u64 a3 = mul2(bw, BXb.y);

        const char* p = tb + (st + g) * 256;
        for (int k = g; k < c; k += 2) {
            float wy = *(const float*)(p + offy);
            float wz = *(const float*)(p + offz);
            ulonglong2 Xa = *(const ulonglong2*)(p + offX);
            ulonglong2 Xb = *(const ulonglong2*)(p + offX + 16);
            u64 ww = pk2(wy * wz);
            a0 = fma2(ww, Xa.x, a0);
            a1 = fma2(ww, Xa.y, a1);
            a2 = fma2(ww, Xb.x, a2);
            a3 = fma2(ww, Xb.y, a3);
            p += 512;
        }

        // Reduction through double-buffered smem (buffer = t & 1).
        ulonglong2* buf = reinterpret_cast<ulonglong2*>(&red[t & 1][rest * 8]);
        if (g) {
            buf[0] = make_ulonglong2(a0, a1);
            buf[1] = make_ulonglong2(a2, a3);
        }
        __syncthreads();
        if (!g) {
            ulonglong2 r0 = buf[0], r1 = buf[1];
            a0 = add2(a0, r0.x); a1 = add2(a1, r0.y);
            a2 = add2(a2, r1.x); a3 = add2(a3, r1.y);

            float f0, f1, f2, f3, f4, f5, f6, f7;
            unpk(a0, f0, f1); unpk(a1, f2, f3);
            unpk(a2, f4, f5); unpk(a3, f6, f7);
            __stcs(op,        f0);
            __stcs(op +  256, f1);
            __stcs(op +  512, f2);
            __stcs(op +  768, f3);
            __stcs(op + 1024, f4);
            __stcs(op + 1280, f5);
            __stcs(op + 1536, f6);
            __stcs(op + 1792, f7);
        }
        op += 2 * 4096;                // next type channel
    }
}

extern "C" void kernel_launch(void* const* d_in, const int* in_sizes, int n_in,
                              void* d_out, int out_size) {
    const float* dist = nullptr;
    const float* sig  = nullptr;
    const int*   an   = nullptr;
    for (int i = 0; i < n_in; i++) {
        if (in_sizes[i] == 1)          sig  = (const float*)d_in[i];
        else if (in_sizes[i] == 24576) dist = (const float*)d_in[i];
        else if (in_sizes[i] == 8192)  an   = (const int*)d_in[i];
    }
    if (!dist) dist = (const float*)d_in[0];
    if (!sig)  sig  = (const float*)d_in[1];
    if (!an)   an   = (const int*)d_in[2];

    mbv_kernel<<<512, NT>>>(dist, sig, an, (float*)d_out);
}